// round 9
// baseline (speedup 1.0000x reference)
#include <cuda_runtime.h>
#include <math.h>

// Problem constants
constexpr int DIMQ   = 16;
constexpr int TSTEPS = 200;
constexpr int NROTS  = 40;
constexpr int DEG    = 3;
constexpr int BLK    = 224;   // 7 warps
constexpr int NWARP  = BLK / 32;
constexpr int SST    = 200;   // smem coefficient stride (active threads only)

// dynamic smem layout (floats):
//   [0, 64*SST)         per-thread gate coefficients, i-major (stride SST)
//   [64*SST, +NWARP*32) warp-reduction buffer
//   then st_s[32], acc_s[32]
constexpr int COEF_FLOATS = 64 * SST;
constexpr int SMEM_FLOATS = COEF_FLOATS + NWARP * 32 + 32 + 32;
constexpr int SMEM_BYTES  = SMEM_FLOATS * 4;

typedef unsigned long long ull;

// ---------- packed f32x2 helpers ----------
__device__ __forceinline__ ull pack2(float lo, float hi) {
    ull r;
    asm("mov.b64 %0, {%1, %2};" : "=l"(r) : "r"(__float_as_uint(lo)), "r"(__float_as_uint(hi)));
    return r;
}
__device__ __forceinline__ ull bc2(float x) { return pack2(x, x); }
__device__ __forceinline__ void unpack2(ull v, float& lo, float& hi) {
    unsigned a, b;
    asm("mov.b64 {%0, %1}, %2;" : "=r"(a), "=r"(b) : "l"(v));
    lo = __uint_as_float(a); hi = __uint_as_float(b);
}
__device__ __forceinline__ ull swap2(ull v) {
    ull r;
    asm("{\n\t.reg .b32 lo, hi;\n\tmov.b64 {lo, hi}, %1;\n\tmov.b64 %0, {hi, lo};\n\t}"
        : "=l"(r) : "l"(v));
    return r;
}
__device__ __forceinline__ ull fma2(ull a, ull b, ull c) {
    ull d; asm("fma.rn.f32x2 %0, %1, %2, %3;" : "=l"(d) : "l"(a), "l"(b), "l"(c)); return d;
}
__device__ __forceinline__ ull mul2(ull a, ull b) {
    ull d; asm("mul.rn.f32x2 %0, %1, %2;" : "=l"(d) : "l"(a), "l"(b)); return d;
}
__device__ __forceinline__ ull add2(ull a, ull b) {
    ull d; asm("add.rn.f32x2 %0, %1, %2;" : "=l"(d) : "l"(a), "l"(b)); return d;
}

// ---------- fused single-qubit gate coefficients ----------
struct U2 { float ar, ai, br, bi; };

__device__ __forceinline__ U2 make_u3(float hx, float hy, float hz) {
    float sx, cx, sy, cy, sz, cz;
    __sincosf(hx, &sx, &cx);
    __sincosf(hy, &sy, &cy);
    __sincosf(hz, &sz, &cz);
    float cycx = cy * cx, sysx = sy * sx, sycx = sy * cx, cysx = cy * sx;
    U2 u;
    u.ar = cz * cycx + sz * sysx;
    u.ai = cz * sysx - sz * cycx;
    u.br = -(cz * sycx + sz * cysx);
    u.bi = sz * sycx - cz * cysx;
    return u;
}

// ---------- packed gate applications ----------
// State: PR[j] = (re[2j], re[2j+1]), PI[j] = (im[2j], im[2j+1]), j=0..7
// Coefficients from smem pointer g, i-major: entry i at g[i*SST].

template <int PB>
__device__ __forceinline__ void u_hi(ull* PR, ull* PI, const float* g) {
    const float g0 = g[0 * SST], g1 = g[1 * SST], g2 = g[2 * SST], g3 = g[3 * SST];
    ull ar  = bc2(g0),  ai  = bc2(g1),  br  = bc2(g2),  bi = bc2(g3);
    ull nai = bc2(-g1), nbr = bc2(-g2), nbi = bc2(-g3);
#pragma unroll
    for (int j = 0; j < 8; ++j) if (!(j & PB)) {
        const int j1 = j | PB;
        ull x0r = PR[j], x0i = PI[j], x1r = PR[j1], x1i = PI[j1];
        PR[j]  = fma2(ar,  x0r, fma2(nai, x0i, fma2(br, x1r, mul2(nbi, x1i))));
        PI[j]  = fma2(ar,  x0i, fma2(ai,  x0r, fma2(br, x1i, mul2(bi,  x1r))));
        PR[j1] = fma2(nbr, x0r, fma2(nbi, x0i, fma2(ar, x1r, mul2(ai,  x1i))));
        PI[j1] = fma2(bi,  x0r, fma2(nbr, x0i, fma2(ar, x1i, mul2(nai, x1r))));
    }
}

__device__ __forceinline__ void u_b1(ull* PR, ull* PI, const float* g) {
    const float ar = g[0 * SST], ai = g[1 * SST], br = g[2 * SST], bi = g[3 * SST];
    ull arar   = bc2(ar);
    ull brnbr  = pack2(br, -br);
    ull naiai  = pack2(-ai, ai);
    ull nbinbi = bc2(-bi);
    ull ainai  = pack2(ai, -ai);
    ull bibi   = bc2(bi);
#pragma unroll
    for (int j = 0; j < 8; ++j) {
        ull SR = PR[j], SI = PI[j];
        ull sSR = swap2(SR), sSI = swap2(SI);
        PR[j] = fma2(arar, SR, fma2(brnbr, sSR, fma2(naiai, SI, mul2(nbinbi, sSI))));
        PI[j] = fma2(arar, SI, fma2(brnbr, sSI, fma2(ainai, SR, mul2(bibi,  sSR))));
    }
}

template <int PCB, int PTB>
__device__ __forceinline__ void crx_hh(ull* PR, ull* PI, const float* g) {
    const float c = g[0], s = g[SST];
    ull c2 = bc2(c), s2 = bc2(s), ns2 = bc2(-s);
#pragma unroll
    for (int j = 0; j < 8; ++j) if ((j & PCB) && !(j & PTB)) {
        const int j1 = j | PTB;
        ull a0r = PR[j], a0i = PI[j], a1r = PR[j1], a1i = PI[j1];
        PR[j]  = fma2(c2, a0r, mul2(s2,  a1i));
        PI[j]  = fma2(c2, a0i, mul2(ns2, a1r));
        PR[j1] = fma2(c2, a1r, mul2(s2,  a0i));
        PI[j1] = fma2(c2, a1i, mul2(ns2, a0r));
    }
}

template <int PTB>
__device__ __forceinline__ void crx_c1(ull* PR, ull* PI, const float* g) {
    const float c = g[0], s = g[SST];
    ull oc  = pack2(1.0f, c);
    ull zs  = pack2(0.0f, s);
    ull zns = pack2(0.0f, -s);
#pragma unroll
    for (int j = 0; j < 8; ++j) if (!(j & PTB)) {
        const int j1 = j | PTB;
        ull a0r = PR[j], a0i = PI[j], a1r = PR[j1], a1i = PI[j1];
        PR[j]  = fma2(oc, a0r, mul2(zs,  a1i));
        PI[j]  = fma2(oc, a0i, mul2(zns, a1r));
        PR[j1] = fma2(oc, a1r, mul2(zs,  a0i));
        PI[j1] = fma2(oc, a1i, mul2(zns, a0r));
    }
}

template <int PCB>
__device__ __forceinline__ void crx_t1(ull* PR, ull* PI, const float* g) {
    const float c = g[0], s = g[SST];
    ull c2 = bc2(c), s2 = bc2(s), ns2 = bc2(-s);
#pragma unroll
    for (int j = 0; j < 8; ++j) if (j & PCB) {
        ull SR = PR[j], SI = PI[j];
        PR[j] = fma2(c2, SR, mul2(s2,  swap2(SI)));
        PI[j] = fma2(c2, SI, mul2(ns2, swap2(SR)));
    }
}

// U-gate portion of one layer (entries 0..15)
__device__ __forceinline__ void layer_u(ull* PR, ull* PI, const float* p) {
    u_hi<4>(PR, PI, p + 0 * SST);    // wire0, BIT8
    u_hi<2>(PR, PI, p + 4 * SST);    // wire1, BIT4
    u_hi<1>(PR, PI, p + 8 * SST);    // wire2, BIT2
    u_b1   (PR, PI, p + 12 * SST);   // wire3, BIT1
}
// CRX portion of one layer (entries 16..31)
__device__ __forceinline__ void layer_crx(ull* PR, ull* PI, const float* p) {
    crx_hh<4, 2>(PR, PI, p + 16 * SST);   // crx<8,4>
    crx_hh<2, 1>(PR, PI, p + 18 * SST);   // crx<4,2>
    crx_t1<1>   (PR, PI, p + 20 * SST);   // crx<2,1>
    crx_c1<4>   (PR, PI, p + 22 * SST);   // crx<1,8>
    crx_c1<1>   (PR, PI, p + 24 * SST);   // crx<1,2>
    crx_hh<1, 2>(PR, PI, p + 26 * SST);   // crx<2,4>
    crx_hh<2, 4>(PR, PI, p + 28 * SST);   // crx<4,8>
    crx_t1<4>   (PR, PI, p + 30 * SST);   // crx<8,1>
}
__device__ __forceinline__ void layer_packed(ull* PR, ull* PI, const float* p) {
    layer_u(PR, PI, p);
    layer_crx(PR, PI, p);
}

// Sparse k=1 prologue: state after 4 U gates applied to |0> is a tensor
// product of first columns: f_w(0) = (ar, ai), f_w(1) = (-br, bi).
__device__ __forceinline__ void product_state(ull* PR, ull* PI, const float* p) {
    // wires 0..2 scalar columns
    float f0r[2], f0i[2], f1r[2], f1i[2], f2r[2], f2i[2];
    {
        const float* g = p;
        f0r[0] = g[0]; f0i[0] = g[SST]; f0r[1] = -g[2 * SST]; f0i[1] = g[3 * SST];
        g = p + 4 * SST;
        f1r[0] = g[0]; f1i[0] = g[SST]; f1r[1] = -g[2 * SST]; f1i[1] = g[3 * SST];
        g = p + 8 * SST;
        f2r[0] = g[0]; f2i[0] = g[SST]; f2r[1] = -g[2 * SST]; f2i[1] = g[3 * SST];
    }
    // wire 3 packed into lanes
    const float* g3 = p + 12 * SST;
    ull F3r = pack2(g3[0], -g3[2 * SST]);
    ull F3i = pack2(g3[SST], g3[3 * SST]);

    // g012[j] = f0(b0)*f1(b1)*f2(b2), j = b0*4 + b1*2 + b2
    float gr[8], gi[8];
#pragma unroll
    for (int b0 = 0; b0 < 2; ++b0)
#pragma unroll
    for (int b1 = 0; b1 < 2; ++b1) {
        float ar01 = f0r[b0] * f1r[b1] - f0i[b0] * f1i[b1];
        float ai01 = f0r[b0] * f1i[b1] + f0i[b0] * f1r[b1];
#pragma unroll
        for (int b2 = 0; b2 < 2; ++b2) {
            int j = b0 * 4 + b1 * 2 + b2;
            gr[j] = ar01 * f2r[b2] - ai01 * f2i[b2];
            gi[j] = ar01 * f2i[b2] + ai01 * f2r[b2];
        }
    }
#pragma unroll
    for (int j = 0; j < 8; ++j) {
        ull grj = bc2(gr[j]), gij = bc2(gi[j]), ngij = bc2(-gi[j]);
        PR[j] = fma2(grj, F3r, mul2(ngij, F3i));
        PI[j] = fma2(grj, F3i, mul2(gij,  F3r));
    }
}

// ---------- scalar versions for the tiny final stage ----------
template <int BIT>
__device__ __forceinline__ void apply_u_sc(float* sr, float* si, U2 u) {
#pragma unroll
    for (int m = 0; m < DIMQ; ++m) if (!(m & BIT)) {
        const int m1 = m | BIT;
        float x0r = sr[m], x0i = si[m], x1r = sr[m1], x1i = si[m1];
        sr[m]  =  u.ar * x0r - u.ai * x0i + u.br * x1r - u.bi * x1i;
        si[m]  =  u.ar * x0i + u.ai * x0r + u.br * x1i + u.bi * x1r;
        sr[m1] = -u.br * x0r - u.bi * x0i + u.ar * x1r + u.ai * x1i;
        si[m1] =  u.bi * x0r - u.br * x0i + u.ar * x1i - u.ai * x1r;
    }
}
template <int CB, int TB>
__device__ __forceinline__ void apply_crx_sc(float* sr, float* si, float h) {
    float s, c;
    __sincosf(h, &s, &c);
#pragma unroll
    for (int m = 0; m < DIMQ; ++m) if ((m & CB) && !(m & TB)) {
        const int m1 = m | TB;
        float a0r = sr[m], a0i = si[m], a1r = sr[m1], a1i = si[m1];
        sr[m]  = c * a0r + s * a1i;
        si[m]  = c * a0i - s * a1r;
        sr[m1] = c * a1r + s * a0i;
        si[m1] = c * a1i - s * a0r;
    }
}
__device__ __forceinline__ void ansatz_layer_sc(float* sr, float* si, const float* hp) {
    apply_u_sc<8>(sr, si, make_u3(hp[0], hp[1], hp[2]));
    apply_u_sc<4>(sr, si, make_u3(hp[3], hp[4], hp[5]));
    apply_u_sc<2>(sr, si, make_u3(hp[6], hp[7], hp[8]));
    apply_u_sc<1>(sr, si, make_u3(hp[9], hp[10], hp[11]));
    apply_crx_sc<8, 4>(sr, si, hp[12]);
    apply_crx_sc<4, 2>(sr, si, hp[13]);
    apply_crx_sc<2, 1>(sr, si, hp[14]);
    apply_crx_sc<1, 8>(sr, si, hp[15]);
    apply_crx_sc<1, 2>(sr, si, hp[16]);
    apply_crx_sc<2, 4>(sr, si, hp[17]);
    apply_crx_sc<4, 8>(sr, si, hp[18]);
    apply_crx_sc<8, 1>(sr, si, hp[19]);
}

__global__ __launch_bounds__(BLK, 4)
void qcore_kernel(const float* __restrict__ tp,    // (B, T, 40)
                  const float* __restrict__ pc,    // (4,)
                  const float* __restrict__ mre,   // (T,)
                  const float* __restrict__ mim,   // (T,)
                  const float* __restrict__ qff,   // (20,)
                  float* __restrict__ out)         // (B, 12)
{
    extern __shared__ float smem[];
    float* coef  = smem;                       // 64*SST
    float* red   = smem + COEF_FLOATS;         // NWARP*32
    float* st_s  = red + NWARP * 32;           // 32
    float* acc_s = st_s + 32;                  // 32

    const int b    = blockIdx.x;
    const int tid  = threadIdx.x;
    const int lane = tid & 31;
    const int wid  = tid >> 5;

    if (tid < 32) {
        float v = (tid == 0) ? 1.0f : 0.0f;
        st_s[tid]  = v;
        acc_s[tid] = pc[0] * v;
    }

    const bool active = (tid < TSTEPS);
    float cr = 0.0f, ci = 0.0f;
    if (active) {
        cr = mre[tid];
        ci = mim[tid];
        float hp[NROTS];
        const float4* p4 = (const float4*)(tp + ((size_t)b * TSTEPS + tid) * NROTS);
#pragma unroll
        for (int i = 0; i < NROTS / 4; ++i) {
            float4 v = p4[i];
            hp[4 * i + 0] = 0.5f * v.x;
            hp[4 * i + 1] = 0.5f * v.y;
            hp[4 * i + 2] = 0.5f * v.z;
            hp[4 * i + 3] = 0.5f * v.w;
        }
        // precompute gate coefficients into smem (i-major, conflict-free)
        float* w = coef + tid;
#pragma unroll
        for (int L = 0; L < 2; ++L) {
            const int base = 20 * L;
            const int cbase = 32 * L;
#pragma unroll
            for (int q = 0; q < 4; ++q) {
                U2 u = make_u3(hp[base + 3 * q], hp[base + 3 * q + 1], hp[base + 3 * q + 2]);
                w[(cbase + 4 * q + 0) * SST] = u.ar;
                w[(cbase + 4 * q + 1) * SST] = u.ai;
                w[(cbase + 4 * q + 2) * SST] = u.br;
                w[(cbase + 4 * q + 3) * SST] = u.bi;
            }
#pragma unroll
            for (int r = 0; r < 8; ++r) {
                float s, c;
                __sincosf(hp[base + 12 + r], &s, &c);
                w[(cbase + 16 + 2 * r + 0) * SST] = c;
                w[(cbase + 16 + 2 * r + 1) * SST] = s;
            }
        }
    }
    __syncthreads();

    const unsigned FULL = 0xffffffffu;
    const float* cp0 = coef + tid;
    const float* cp1 = coef + 32 * SST + tid;

    for (int k = 1; k <= DEG; ++k) {
        ull PR[8], PI[8];
        if (active) {
            if (k == 1) {
                // |0> input: state after the 4 U gates is a tensor product
                product_state(PR, PI, cp0);
            } else {
#pragma unroll
                for (int j = 0; j < 8; ++j) {
                    PR[j] = pack2(st_s[2 * j],      st_s[2 * j + 1]);
                    PI[j] = pack2(st_s[16 + 2 * j], st_s[17 + 2 * j]);
                }
                layer_u(PR, PI, cp0);
            }
            layer_crx(PR, PI, cp0);
            layer_packed(PR, PI, cp1);
            // weight by complex coeff (cr + i ci)
            ull crp = bc2(cr), cip = bc2(ci), ncip = bc2(-ci);
#pragma unroll
            for (int j = 0; j < 8; ++j) {
                ull r0 = PR[j], i0 = PI[j];
                PR[j] = fma2(crp, r0, mul2(ncip, i0));
                PI[j] = fma2(crp, i0, mul2(cip,  r0));
            }
        } else {
#pragma unroll
            for (int j = 0; j < 8; ++j) { PR[j] = 0ull; PI[j] = 0ull; }
        }

        // ---- register-exchange butterfly: lane L ends with component L ----
        ull W[8];
        {
            const bool up = (lane & 16);
#pragma unroll
            for (int j = 0; j < 8; ++j) {
                ull keep = up ? PI[j] : PR[j];
                ull give = up ? PR[j] : PI[j];
                W[j] = add2(keep, __shfl_xor_sync(FULL, give, 16));
            }
        }
        ull X[4];
        {
            const bool up = (lane & 8);
#pragma unroll
            for (int j = 0; j < 4; ++j) {
                ull keep = up ? W[j + 4] : W[j];
                ull give = up ? W[j] : W[j + 4];
                X[j] = add2(keep, __shfl_xor_sync(FULL, give, 8));
            }
        }
        ull Y[2];
        {
            const bool up = (lane & 4);
#pragma unroll
            for (int j = 0; j < 2; ++j) {
                ull keep = up ? X[j + 2] : X[j];
                ull give = up ? X[j] : X[j + 2];
                Y[j] = add2(keep, __shfl_xor_sync(FULL, give, 4));
            }
        }
        ull Z;
        {
            const bool up = (lane & 2);
            ull keep = up ? Y[1] : Y[0];
            ull give = up ? Y[0] : Y[1];
            Z = add2(keep, __shfl_xor_sync(FULL, give, 2));
        }
        float res;
        {
            float zlo, zhi;
            unpack2(Z, zlo, zhi);
            float keep = (lane & 1) ? zhi : zlo;
            float give = (lane & 1) ? zlo : zhi;
            res = keep + __shfl_xor_sync(FULL, give, 1);
        }

        red[wid * 32 + lane] = res;
        __syncthreads();
        if (tid < 32) {
            float s = 0.0f;
#pragma unroll
            for (int w = 0; w < NWARP; ++w) s += red[w * 32 + tid];
            st_s[tid] = s;
            acc_s[tid] += pc[k] * s;
        }
        __syncthreads();
    }

    // ---- final stage: normalize, qff ansatz, expectation values (thread 0) ----
    if (tid == 0) {
        float l1 = fabsf(pc[0]) + fabsf(pc[1]) + fabsf(pc[2]) + fabsf(pc[3]);
        float inv_l1 = 1.0f / l1;
        float ar[DIMQ], ai[DIMQ];
        float ss = 0.0f;
#pragma unroll
        for (int j = 0; j < DIMQ; ++j) {
            ar[j] = acc_s[j] * inv_l1;
            ai[j] = acc_s[16 + j] * inv_l1;
            ss += ar[j] * ar[j] + ai[j] * ai[j];
        }
        float inv_n = 1.0f / (sqrtf(ss) + 1e-9f);
#pragma unroll
        for (int j = 0; j < DIMQ; ++j) { ar[j] *= inv_n; ai[j] *= inv_n; }

        float qh[20];
#pragma unroll
        for (int i = 0; i < 20; ++i) qh[i] = 0.5f * qff[i];
        ansatz_layer_sc(ar, ai, qh);

#pragma unroll
        for (int w = 0; w < 4; ++w) {
            const int bit = 8 >> w;
            float x = 0.0f, y = 0.0f, z = 0.0f;
#pragma unroll
            for (int m = 0; m < DIMQ; ++m) {
                if (!(m & bit)) {
                    const int m1 = m | bit;
                    float zr = ar[m] * ar[m1] + ai[m] * ai[m1];
                    float zi = ar[m] * ai[m1] - ai[m] * ar[m1];
                    x += 2.0f * zr;
                    y += 2.0f * zi;
                    z += ar[m] * ar[m] + ai[m] * ai[m]
                       - ar[m1] * ar[m1] - ai[m1] * ai[m1];
                }
            }
            out[b * 12 + w]     = x;
            out[b * 12 + 4 + w] = y;
            out[b * 12 + 8 + w] = z;
        }
    }
}

extern "C" void kernel_launch(void* const* d_in, const int* in_sizes, int n_in,
                              void* d_out, int out_size) {
    const float* tp  = (const float*)d_in[0];
    const float* pc  = (const float*)d_in[1];
    const float* mre = (const float*)d_in[2];
    const float* mim = (const float*)d_in[3];
    const float* qff = (const float*)d_in[4];
    float* out = (float*)d_out;

    cudaFuncSetAttribute(qcore_kernel,
                         cudaFuncAttributeMaxDynamicSharedMemorySize, SMEM_BYTES);

    const int B = in_sizes[0] / (TSTEPS * NROTS);
    qcore_kernel<<<B, BLK, SMEM_BYTES>>>(tp, pc, mre, mim, qff, out);
}

// round 12
// speedup vs baseline: 1.5467x; 1.5467x over previous
#include <cuda_runtime.h>
#include <math.h>

// Problem constants
constexpr int DIMQ   = 16;
constexpr int TSTEPS = 200;
constexpr int NROTS  = 40;
constexpr int DEG    = 3;
constexpr int BLK    = 224;   // 7 warps
constexpr int NWARP  = BLK / 32;
constexpr int SST    = 200;   // smem coefficient stride (active threads only)

// dynamic smem layout (floats):
//   [0, 64*SST)         per-thread gate coefficients, i-major (stride SST)
//   [64*SST, +NWARP*32) warp-reduction buffer
//   then st_s[32], acc_s[32]
constexpr int COEF_FLOATS = 64 * SST;
constexpr int SMEM_FLOATS = COEF_FLOATS + NWARP * 32 + 32 + 32;
constexpr int SMEM_BYTES  = SMEM_FLOATS * 4;

typedef unsigned long long ull;

// ---------- packed f32x2 helpers ----------
__device__ __forceinline__ ull pack2(float lo, float hi) {
    ull r;
    asm("mov.b64 %0, {%1, %2};" : "=l"(r) : "r"(__float_as_uint(lo)), "r"(__float_as_uint(hi)));
    return r;
}
__device__ __forceinline__ ull bc2(float x) { return pack2(x, x); }
__device__ __forceinline__ void unpack2(ull v, float& lo, float& hi) {
    unsigned a, b;
    asm("mov.b64 {%0, %1}, %2;" : "=r"(a), "=r"(b) : "l"(v));
    lo = __uint_as_float(a); hi = __uint_as_float(b);
}
__device__ __forceinline__ ull swap2(ull v) {
    ull r;
    asm("{\n\t.reg .b32 lo, hi;\n\tmov.b64 {lo, hi}, %1;\n\tmov.b64 %0, {hi, lo};\n\t}"
        : "=l"(r) : "l"(v));
    return r;
}
__device__ __forceinline__ ull fma2(ull a, ull b, ull c) {
    ull d; asm("fma.rn.f32x2 %0, %1, %2, %3;" : "=l"(d) : "l"(a), "l"(b), "l"(c)); return d;
}
__device__ __forceinline__ ull mul2(ull a, ull b) {
    ull d; asm("mul.rn.f32x2 %0, %1, %2;" : "=l"(d) : "l"(a), "l"(b)); return d;
}
__device__ __forceinline__ ull add2(ull a, ull b) {
    ull d; asm("add.rn.f32x2 %0, %1, %2;" : "=l"(d) : "l"(a), "l"(b)); return d;
}

// ---------- fused single-qubit gate coefficients ----------
struct U2 { float ar, ai, br, bi; };

__device__ __forceinline__ U2 make_u3(float hx, float hy, float hz) {
    float sx, cx, sy, cy, sz, cz;
    __sincosf(hx, &sx, &cx);
    __sincosf(hy, &sy, &cy);
    __sincosf(hz, &sz, &cz);
    float cycx = cy * cx, sysx = sy * sx, sycx = sy * cx, cysx = cy * sx;
    U2 u;
    u.ar = cz * cycx + sz * sysx;
    u.ai = cz * sysx - sz * cycx;
    u.br = -(cz * sycx + sz * cysx);
    u.bi = sz * sycx - cz * cysx;
    return u;
}

// ---------- packed gate applications ----------
// State: PR[j] = (re[2j], re[2j+1]), PI[j] = (im[2j], im[2j+1]), j=0..7
// Coefficients from smem pointer g, i-major: entry i at g[i*SST].

template <int PB>
__device__ __forceinline__ void u_hi(ull* PR, ull* PI, const float* g) {
    const float g0 = g[0 * SST], g1 = g[1 * SST], g2 = g[2 * SST], g3 = g[3 * SST];
    ull ar  = bc2(g0),  ai  = bc2(g1),  br  = bc2(g2),  bi = bc2(g3);
    ull nai = bc2(-g1), nbr = bc2(-g2), nbi = bc2(-g3);
#pragma unroll
    for (int j = 0; j < 8; ++j) if (!(j & PB)) {
        const int j1 = j | PB;
        ull x0r = PR[j], x0i = PI[j], x1r = PR[j1], x1i = PI[j1];
        PR[j]  = fma2(ar,  x0r, fma2(nai, x0i, fma2(br, x1r, mul2(nbi, x1i))));
        PI[j]  = fma2(ar,  x0i, fma2(ai,  x0r, fma2(br, x1i, mul2(bi,  x1r))));
        PR[j1] = fma2(nbr, x0r, fma2(nbi, x0i, fma2(ar, x1r, mul2(ai,  x1i))));
        PI[j1] = fma2(bi,  x0r, fma2(nbr, x0i, fma2(ar, x1i, mul2(nai, x1r))));
    }
}

__device__ __forceinline__ void u_b1(ull* PR, ull* PI, const float* g) {
    const float ar = g[0 * SST], ai = g[1 * SST], br = g[2 * SST], bi = g[3 * SST];
    ull arar   = bc2(ar);
    ull brnbr  = pack2(br, -br);
    ull naiai  = pack2(-ai, ai);
    ull nbinbi = bc2(-bi);
    ull ainai  = pack2(ai, -ai);
    ull bibi   = bc2(bi);
#pragma unroll
    for (int j = 0; j < 8; ++j) {
        ull SR = PR[j], SI = PI[j];
        ull sSR = swap2(SR), sSI = swap2(SI);
        PR[j] = fma2(arar, SR, fma2(brnbr, sSR, fma2(naiai, SI, mul2(nbinbi, sSI))));
        PI[j] = fma2(arar, SI, fma2(brnbr, sSI, fma2(ainai, SR, mul2(bibi,  sSR))));
    }
}

template <int PCB, int PTB>
__device__ __forceinline__ void crx_hh(ull* PR, ull* PI, const float* g) {
    const float c = g[0], s = g[SST];
    ull c2 = bc2(c), s2 = bc2(s), ns2 = bc2(-s);
#pragma unroll
    for (int j = 0; j < 8; ++j) if ((j & PCB) && !(j & PTB)) {
        const int j1 = j | PTB;
        ull a0r = PR[j], a0i = PI[j], a1r = PR[j1], a1i = PI[j1];
        PR[j]  = fma2(c2, a0r, mul2(s2,  a1i));
        PI[j]  = fma2(c2, a0i, mul2(ns2, a1r));
        PR[j1] = fma2(c2, a1r, mul2(s2,  a0i));
        PI[j1] = fma2(c2, a1i, mul2(ns2, a0r));
    }
}

template <int PTB>
__device__ __forceinline__ void crx_c1(ull* PR, ull* PI, const float* g) {
    const float c = g[0], s = g[SST];
    ull oc  = pack2(1.0f, c);
    ull zs  = pack2(0.0f, s);
    ull zns = pack2(0.0f, -s);
#pragma unroll
    for (int j = 0; j < 8; ++j) if (!(j & PTB)) {
        const int j1 = j | PTB;
        ull a0r = PR[j], a0i = PI[j], a1r = PR[j1], a1i = PI[j1];
        PR[j]  = fma2(oc, a0r, mul2(zs,  a1i));
        PI[j]  = fma2(oc, a0i, mul2(zns, a1r));
        PR[j1] = fma2(oc, a1r, mul2(zs,  a0i));
        PI[j1] = fma2(oc, a1i, mul2(zns, a0r));
    }
}

template <int PCB>
__device__ __forceinline__ void crx_t1(ull* PR, ull* PI, const float* g) {
    const float c = g[0], s = g[SST];
    ull c2 = bc2(c), s2 = bc2(s), ns2 = bc2(-s);
#pragma unroll
    for (int j = 0; j < 8; ++j) if (j & PCB) {
        ull SR = PR[j], SI = PI[j];
        PR[j] = fma2(c2, SR, mul2(s2,  swap2(SI)));
        PI[j] = fma2(c2, SI, mul2(ns2, swap2(SR)));
    }
}

// U-gate portion of one layer (entries 0..15)
__device__ __forceinline__ void layer_u(ull* PR, ull* PI, const float* p) {
    u_hi<4>(PR, PI, p + 0 * SST);    // wire0, BIT8
    u_hi<2>(PR, PI, p + 4 * SST);    // wire1, BIT4
    u_hi<1>(PR, PI, p + 8 * SST);    // wire2, BIT2
    u_b1   (PR, PI, p + 12 * SST);   // wire3, BIT1
}
// CRX portion of one layer (entries 16..31)
__device__ __forceinline__ void layer_crx(ull* PR, ull* PI, const float* p) {
    crx_hh<4, 2>(PR, PI, p + 16 * SST);   // crx<8,4>
    crx_hh<2, 1>(PR, PI, p + 18 * SST);   // crx<4,2>
    crx_t1<1>   (PR, PI, p + 20 * SST);   // crx<2,1>
    crx_c1<4>   (PR, PI, p + 22 * SST);   // crx<1,8>
    crx_c1<1>   (PR, PI, p + 24 * SST);   // crx<1,2>
    crx_hh<1, 2>(PR, PI, p + 26 * SST);   // crx<2,4>
    crx_hh<2, 4>(PR, PI, p + 28 * SST);   // crx<4,8>
    crx_t1<4>   (PR, PI, p + 30 * SST);   // crx<8,1>
}
__device__ __forceinline__ void layer_packed(ull* PR, ull* PI, const float* p) {
    layer_u(PR, PI, p);
    layer_crx(PR, PI, p);
}

// Sparse k=1 prologue: state after 4 U gates applied to |0> is a tensor
// product of first columns: f_w(0) = (ar, ai), f_w(1) = (-br, bi).
__device__ __forceinline__ void product_state(ull* PR, ull* PI, const float* p) {
    float f0r[2], f0i[2], f1r[2], f1i[2], f2r[2], f2i[2];
    {
        const float* g = p;
        f0r[0] = g[0]; f0i[0] = g[SST]; f0r[1] = -g[2 * SST]; f0i[1] = g[3 * SST];
        g = p + 4 * SST;
        f1r[0] = g[0]; f1i[0] = g[SST]; f1r[1] = -g[2 * SST]; f1i[1] = g[3 * SST];
        g = p + 8 * SST;
        f2r[0] = g[0]; f2i[0] = g[SST]; f2r[1] = -g[2 * SST]; f2i[1] = g[3 * SST];
    }
    const float* g3 = p + 12 * SST;
    ull F3r = pack2(g3[0], -g3[2 * SST]);
    ull F3i = pack2(g3[SST], g3[3 * SST]);

    float gr[8], gi[8];
#pragma unroll
    for (int b0 = 0; b0 < 2; ++b0)
#pragma unroll
    for (int b1 = 0; b1 < 2; ++b1) {
        float ar01 = f0r[b0] * f1r[b1] - f0i[b0] * f1i[b1];
        float ai01 = f0r[b0] * f1i[b1] + f0i[b0] * f1r[b1];
#pragma unroll
        for (int b2 = 0; b2 < 2; ++b2) {
            int j = b0 * 4 + b1 * 2 + b2;
            gr[j] = ar01 * f2r[b2] - ai01 * f2i[b2];
            gi[j] = ar01 * f2i[b2] + ai01 * f2r[b2];
        }
    }
#pragma unroll
    for (int j = 0; j < 8; ++j) {
        ull grj = bc2(gr[j]), gij = bc2(gi[j]), ngij = bc2(-gi[j]);
        PR[j] = fma2(grj, F3r, mul2(ngij, F3i));
        PI[j] = fma2(grj, F3i, mul2(gij,  F3r));
    }
}

// ---------- scalar versions for the tiny final stage ----------
template <int BIT>
__device__ __forceinline__ void apply_u_sc(float* sr, float* si, U2 u) {
#pragma unroll
    for (int m = 0; m < DIMQ; ++m) if (!(m & BIT)) {
        const int m1 = m | BIT;
        float x0r = sr[m], x0i = si[m], x1r = sr[m1], x1i = si[m1];
        sr[m]  =  u.ar * x0r - u.ai * x0i + u.br * x1r - u.bi * x1i;
        si[m]  =  u.ar * x0i + u.ai * x0r + u.br * x1i + u.bi * x1r;
        sr[m1] = -u.br * x0r - u.bi * x0i + u.ar * x1r + u.ai * x1i;
        si[m1] =  u.bi * x0r - u.br * x0i + u.ar * x1i - u.ai * x1r;
    }
}
template <int CB, int TB>
__device__ __forceinline__ void apply_crx_sc(float* sr, float* si, float h) {
    float s, c;
    __sincosf(h, &s, &c);
#pragma unroll
    for (int m = 0; m < DIMQ; ++m) if ((m & CB) && !(m & TB)) {
        const int m1 = m | TB;
        float a0r = sr[m], a0i = si[m], a1r = sr[m1], a1i = si[m1];
        sr[m]  = c * a0r + s * a1i;
        si[m]  = c * a0i - s * a1r;
        sr[m1] = c * a1r + s * a0i;
        si[m1] = c * a1i - s * a0r;
    }
}
__device__ __forceinline__ void ansatz_layer_sc(float* sr, float* si, const float* hp) {
    apply_u_sc<8>(sr, si, make_u3(hp[0], hp[1], hp[2]));
    apply_u_sc<4>(sr, si, make_u3(hp[3], hp[4], hp[5]));
    apply_u_sc<2>(sr, si, make_u3(hp[6], hp[7], hp[8]));
    apply_u_sc<1>(sr, si, make_u3(hp[9], hp[10], hp[11]));
    apply_crx_sc<8, 4>(sr, si, hp[12]);
    apply_crx_sc<4, 2>(sr, si, hp[13]);
    apply_crx_sc<2, 1>(sr, si, hp[14]);
    apply_crx_sc<1, 8>(sr, si, hp[15]);
    apply_crx_sc<1, 2>(sr, si, hp[16]);
    apply_crx_sc<2, 4>(sr, si, hp[17]);
    apply_crx_sc<4, 8>(sr, si, hp[18]);
    apply_crx_sc<8, 1>(sr, si, hp[19]);
}

__global__ __launch_bounds__(BLK, 3)
void qcore_kernel(const float* __restrict__ tp,    // (B, T, 40)
                  const float* __restrict__ pc,    // (4,)
                  const float* __restrict__ mre,   // (T,)
                  const float* __restrict__ mim,   // (T,)
                  const float* __restrict__ qff,   // (20,)
                  float* __restrict__ out)         // (B, 12)
{
    extern __shared__ float smem[];
    float* coef  = smem;                       // 64*SST
    float* red   = smem + COEF_FLOATS;         // NWARP*32
    float* st_s  = red + NWARP * 32;           // 32
    float* acc_s = st_s + 32;                  // 32

    const int b    = blockIdx.x;
    const int tid  = threadIdx.x;
    const int lane = tid & 31;
    const int wid  = tid >> 5;

    if (tid < 32) {
        float v = (tid == 0) ? 1.0f : 0.0f;
        st_s[tid]  = v;
        acc_s[tid] = pc[0] * v;
    }

    const bool active = (tid < TSTEPS);
    float cr = 0.0f, ci = 0.0f;
    if (active) {
        cr = mre[tid];
        ci = mim[tid];
        float hp[NROTS];
        const float4* p4 = (const float4*)(tp + ((size_t)b * TSTEPS + tid) * NROTS);
#pragma unroll
        for (int i = 0; i < NROTS / 4; ++i) {
            float4 v = p4[i];
            hp[4 * i + 0] = 0.5f * v.x;
            hp[4 * i + 1] = 0.5f * v.y;
            hp[4 * i + 2] = 0.5f * v.z;
            hp[4 * i + 3] = 0.5f * v.w;
        }
        // precompute gate coefficients into smem (i-major, conflict-free)
        float* w = coef + tid;
#pragma unroll
        for (int L = 0; L < 2; ++L) {
            const int base = 20 * L;
            const int cbase = 32 * L;
#pragma unroll
            for (int q = 0; q < 4; ++q) {
                U2 u = make_u3(hp[base + 3 * q], hp[base + 3 * q + 1], hp[base + 3 * q + 2]);
                w[(cbase + 4 * q + 0) * SST] = u.ar;
                w[(cbase + 4 * q + 1) * SST] = u.ai;
                w[(cbase + 4 * q + 2) * SST] = u.br;
                w[(cbase + 4 * q + 3) * SST] = u.bi;
            }
#pragma unroll
            for (int r = 0; r < 8; ++r) {
                float s, c;
                __sincosf(hp[base + 12 + r], &s, &c);
                w[(cbase + 16 + 2 * r + 0) * SST] = c;
                w[(cbase + 16 + 2 * r + 1) * SST] = s;
            }
        }
    }
    __syncthreads();

    const unsigned FULL = 0xffffffffu;
    const float* cp0 = coef + tid;
    const float* cp1 = coef + 32 * SST + tid;

    for (int k = 1; k <= DEG; ++k) {
        ull PR[8], PI[8];
        if (active) {
            if (k == 1) {
                // |0> input: state after the 4 U gates is a tensor product
                product_state(PR, PI, cp0);
            } else {
#pragma unroll
                for (int j = 0; j < 8; ++j) {
                    PR[j] = pack2(st_s[2 * j],      st_s[2 * j + 1]);
                    PI[j] = pack2(st_s[16 + 2 * j], st_s[17 + 2 * j]);
                }
                layer_u(PR, PI, cp0);
            }
            layer_crx(PR, PI, cp0);
            layer_packed(PR, PI, cp1);
            // weight by complex coeff (cr + i ci)
            ull crp = bc2(cr), cip = bc2(ci), ncip = bc2(-ci);
#pragma unroll
            for (int j = 0; j < 8; ++j) {
                ull r0 = PR[j], i0 = PI[j];
                PR[j] = fma2(crp, r0, mul2(ncip, i0));
                PI[j] = fma2(crp, i0, mul2(cip,  r0));
            }
        } else {
#pragma unroll
            for (int j = 0; j < 8; ++j) { PR[j] = 0ull; PI[j] = 0ull; }
        }

        // ---- register-exchange butterfly: lane L ends with component L ----
        ull W[8];
        {
            const bool up = (lane & 16);
#pragma unroll
            for (int j = 0; j < 8; ++j) {
                ull keep = up ? PI[j] : PR[j];
                ull give = up ? PR[j] : PI[j];
                W[j] = add2(keep, __shfl_xor_sync(FULL, give, 16));
            }
        }
        ull X[4];
        {
            const bool up = (lane & 8);
#pragma unroll
            for (int j = 0; j < 4; ++j) {
                ull keep = up ? W[j + 4] : W[j];
                ull give = up ? W[j] : W[j + 4];
                X[j] = add2(keep, __shfl_xor_sync(FULL, give, 8));
            }
        }
        ull Y[2];
        {
            const bool up = (lane & 4);
#pragma unroll
            for (int j = 0; j < 2; ++j) {
                ull keep = up ? X[j + 2] : X[j];
                ull give = up ? X[j] : X[j + 2];
                Y[j] = add2(keep, __shfl_xor_sync(FULL, give, 4));
            }
        }
        ull Z;
        {
            const bool up = (lane & 2);
            ull keep = up ? Y[1] : Y[0];
            ull give = up ? Y[0] : Y[1];
            Z = add2(keep, __shfl_xor_sync(FULL, give, 2));
        }
        float res;
        {
            float zlo, zhi;
            unpack2(Z, zlo, zhi);
            float keep = (lane & 1) ? zhi : zlo;
            float give = (lane & 1) ? zlo : zhi;
            res = keep + __shfl_xor_sync(FULL, give, 1);
        }

        red[wid * 32 + lane] = res;
        __syncthreads();
        if (tid < 32) {
            float s = 0.0f;
#pragma unroll
            for (int w = 0; w < NWARP; ++w) s += red[w * 32 + tid];
            st_s[tid] = s;
            acc_s[tid] += pc[k] * s;
        }
        __syncthreads();
    }

    // ---- final stage: normalize, qff ansatz, expectation values (thread 0) ----
    if (tid == 0) {
        float l1 = fabsf(pc[0]) + fabsf(pc[1]) + fabsf(pc[2]) + fabsf(pc[3]);
        float inv_l1 = 1.0f / l1;
        float ar[DIMQ], ai[DIMQ];
        float ss = 0.0f;
#pragma unroll
        for (int j = 0; j < DIMQ; ++j) {
            ar[j] = acc_s[j] * inv_l1;
            ai[j] = acc_s[16 + j] * inv_l1;
            ss += ar[j] * ar[j] + ai[j] * ai[j];
        }
        float inv_n = 1.0f / (sqrtf(ss) + 1e-9f);
#pragma unroll
        for (int j = 0; j < DIMQ; ++j) { ar[j] *= inv_n; ai[j] *= inv_n; }

        float qh[20];
#pragma unroll
        for (int i = 0; i < 20; ++i) qh[i] = 0.5f * qff[i];
        ansatz_layer_sc(ar, ai, qh);

#pragma unroll
        for (int w = 0; w < 4; ++w) {
            const int bit = 8 >> w;
            float x = 0.0f, y = 0.0f, z = 0.0f;
#pragma unroll
            for (int m = 0; m < DIMQ; ++m) {
                if (!(m & bit)) {
                    const int m1 = m | bit;
                    float zr = ar[m] * ar[m1] + ai[m] * ai[m1];
                    float zi = ar[m] * ai[m1] - ai[m] * ar[m1];
                    x += 2.0f * zr;
                    y += 2.0f * zi;
                    z += ar[m] * ar[m] + ai[m] * ai[m]
                       - ar[m1] * ar[m1] - ai[m1] * ai[m1];
                }
            }
            out[b * 12 + w]     = x;
            out[b * 12 + 4 + w] = y;
            out[b * 12 + 8 + w] = z;
        }
    }
}

extern "C" void kernel_launch(void* const* d_in, const int* in_sizes, int n_in,
                              void* d_out, int out_size) {
    const float* tp  = (const float*)d_in[0];
    const float* pc  = (const float*)d_in[1];
    const float* mre = (const float*)d_in[2];
    const float* mim = (const float*)d_in[3];
    const float* qff = (const float*)d_in[4];
    float* out = (float*)d_out;

    cudaFuncSetAttribute(qcore_kernel,
                         cudaFuncAttributeMaxDynamicSharedMemorySize, SMEM_BYTES);

    const int B = in_sizes[0] / (TSTEPS * NROTS);
    qcore_kernel<<<B, BLK, SMEM_BYTES>>>(tp, pc, mre, mim, qff, out);
}

// round 16
// speedup vs baseline: 1.6368x; 1.0583x over previous
#include <cuda_runtime.h>
#include <math.h>

// Problem constants
constexpr int DIMQ   = 16;
constexpr int TSTEPS = 200;
constexpr int NROTS  = 40;
constexpr int DEG    = 3;
constexpr int BLK    = 256;   // 8 warps (200 active threads + padding)
constexpr int NWARP  = BLK / 32;
constexpr int SST    = 200;   // smem coefficient stride (active threads only)

// dynamic smem layout (floats):
//   [0, 64*SST)         per-thread gate coefficients, i-major (stride SST)
//   [64*SST, +NWARP*32) warp-reduction buffer
//   then st_s[32], acc_s[32]
constexpr int COEF_FLOATS = 64 * SST;
constexpr int SMEM_FLOATS = COEF_FLOATS + NWARP * 32 + 32 + 32;
constexpr int SMEM_BYTES  = SMEM_FLOATS * 4;

typedef unsigned long long ull;

// ---------- packed f32x2 helpers ----------
__device__ __forceinline__ ull pack2(float lo, float hi) {
    ull r;
    asm("mov.b64 %0, {%1, %2};" : "=l"(r) : "r"(__float_as_uint(lo)), "r"(__float_as_uint(hi)));
    return r;
}
__device__ __forceinline__ ull bc2(float x) { return pack2(x, x); }
__device__ __forceinline__ void unpack2(ull v, float& lo, float& hi) {
    unsigned a, b;
    asm("mov.b64 {%0, %1}, %2;" : "=r"(a), "=r"(b) : "l"(v));
    lo = __uint_as_float(a); hi = __uint_as_float(b);
}
__device__ __forceinline__ ull swap2(ull v) {
    ull r;
    asm("{\n\t.reg .b32 lo, hi;\n\tmov.b64 {lo, hi}, %1;\n\tmov.b64 %0, {hi, lo};\n\t}"
        : "=l"(r) : "l"(v));
    return r;
}
__device__ __forceinline__ ull fma2(ull a, ull b, ull c) {
    ull d; asm("fma.rn.f32x2 %0, %1, %2, %3;" : "=l"(d) : "l"(a), "l"(b), "l"(c)); return d;
}
__device__ __forceinline__ ull mul2(ull a, ull b) {
    ull d; asm("mul.rn.f32x2 %0, %1, %2;" : "=l"(d) : "l"(a), "l"(b)); return d;
}
__device__ __forceinline__ ull add2(ull a, ull b) {
    ull d; asm("add.rn.f32x2 %0, %1, %2;" : "=l"(d) : "l"(a), "l"(b)); return d;
}

// ---------- fused single-qubit gate coefficients ----------
struct U2 { float ar, ai, br, bi; };

__device__ __forceinline__ U2 make_u3(float hx, float hy, float hz) {
    float sx, cx, sy, cy, sz, cz;
    __sincosf(hx, &sx, &cx);
    __sincosf(hy, &sy, &cy);
    __sincosf(hz, &sz, &cz);
    float cycx = cy * cx, sysx = sy * sx, sycx = sy * cx, cysx = cy * sx;
    U2 u;
    u.ar = cz * cycx + sz * sysx;
    u.ai = cz * sysx - sz * cycx;
    u.br = -(cz * sycx + sz * cysx);
    u.bi = sz * sycx - cz * cysx;
    return u;
}

// ---------- packed gate applications ----------
// State: PR[j] = (re[2j], re[2j+1]), PI[j] = (im[2j], im[2j+1]), j=0..7
// Coefficients from smem pointer g, i-major: entry i at g[i*SST].

template <int PB>
__device__ __forceinline__ void u_hi(ull* PR, ull* PI, const float* g) {
    const float g0 = g[0 * SST], g1 = g[1 * SST], g2 = g[2 * SST], g3 = g[3 * SST];
    ull ar  = bc2(g0),  ai  = bc2(g1),  br  = bc2(g2),  bi = bc2(g3);
    ull nai = bc2(-g1), nbr = bc2(-g2), nbi = bc2(-g3);
#pragma unroll
    for (int j = 0; j < 8; ++j) if (!(j & PB)) {
        const int j1 = j | PB;
        ull x0r = PR[j], x0i = PI[j], x1r = PR[j1], x1i = PI[j1];
        PR[j]  = fma2(ar,  x0r, fma2(nai, x0i, fma2(br, x1r, mul2(nbi, x1i))));
        PI[j]  = fma2(ar,  x0i, fma2(ai,  x0r, fma2(br, x1i, mul2(bi,  x1r))));
        PR[j1] = fma2(nbr, x0r, fma2(nbi, x0i, fma2(ar, x1r, mul2(ai,  x1i))));
        PI[j1] = fma2(bi,  x0r, fma2(nbr, x0i, fma2(ar, x1i, mul2(nai, x1r))));
    }
}

__device__ __forceinline__ void u_b1(ull* PR, ull* PI, const float* g) {
    const float ar = g[0 * SST], ai = g[1 * SST], br = g[2 * SST], bi = g[3 * SST];
    ull arar   = bc2(ar);
    ull brnbr  = pack2(br, -br);
    ull naiai  = pack2(-ai, ai);
    ull nbinbi = bc2(-bi);
    ull ainai  = pack2(ai, -ai);
    ull bibi   = bc2(bi);
#pragma unroll
    for (int j = 0; j < 8; ++j) {
        ull SR = PR[j], SI = PI[j];
        ull sSR = swap2(SR), sSI = swap2(SI);
        PR[j] = fma2(arar, SR, fma2(brnbr, sSR, fma2(naiai, SI, mul2(nbinbi, sSI))));
        PI[j] = fma2(arar, SI, fma2(brnbr, sSI, fma2(ainai, SR, mul2(bibi,  sSR))));
    }
}

template <int PCB, int PTB>
__device__ __forceinline__ void crx_hh(ull* PR, ull* PI, const float* g) {
    const float c = g[0], s = g[SST];
    ull c2 = bc2(c), s2 = bc2(s), ns2 = bc2(-s);
#pragma unroll
    for (int j = 0; j < 8; ++j) if ((j & PCB) && !(j & PTB)) {
        const int j1 = j | PTB;
        ull a0r = PR[j], a0i = PI[j], a1r = PR[j1], a1i = PI[j1];
        PR[j]  = fma2(c2, a0r, mul2(s2,  a1i));
        PI[j]  = fma2(c2, a0i, mul2(ns2, a1r));
        PR[j1] = fma2(c2, a1r, mul2(s2,  a0i));
        PI[j1] = fma2(c2, a1i, mul2(ns2, a0r));
    }
}

template <int PTB>
__device__ __forceinline__ void crx_c1(ull* PR, ull* PI, const float* g) {
    const float c = g[0], s = g[SST];
    ull oc  = pack2(1.0f, c);
    ull zs  = pack2(0.0f, s);
    ull zns = pack2(0.0f, -s);
#pragma unroll
    for (int j = 0; j < 8; ++j) if (!(j & PTB)) {
        const int j1 = j | PTB;
        ull a0r = PR[j], a0i = PI[j], a1r = PR[j1], a1i = PI[j1];
        PR[j]  = fma2(oc, a0r, mul2(zs,  a1i));
        PI[j]  = fma2(oc, a0i, mul2(zns, a1r));
        PR[j1] = fma2(oc, a1r, mul2(zs,  a0i));
        PI[j1] = fma2(oc, a1i, mul2(zns, a0r));
    }
}

template <int PCB>
__device__ __forceinline__ void crx_t1(ull* PR, ull* PI, const float* g) {
    const float c = g[0], s = g[SST];
    ull c2 = bc2(c), s2 = bc2(s), ns2 = bc2(-s);
#pragma unroll
    for (int j = 0; j < 8; ++j) if (j & PCB) {
        ull SR = PR[j], SI = PI[j];
        PR[j] = fma2(c2, SR, mul2(s2,  swap2(SI)));
        PI[j] = fma2(c2, SI, mul2(ns2, swap2(SR)));
    }
}

// U-gate portion of one layer (entries 0..15)
__device__ __forceinline__ void layer_u(ull* PR, ull* PI, const float* p) {
    u_hi<4>(PR, PI, p + 0 * SST);    // wire0, BIT8
    u_hi<2>(PR, PI, p + 4 * SST);    // wire1, BIT4
    u_hi<1>(PR, PI, p + 8 * SST);    // wire2, BIT2
    u_b1   (PR, PI, p + 12 * SST);   // wire3, BIT1
}
// CRX portion of one layer (entries 16..31)
__device__ __forceinline__ void layer_crx(ull* PR, ull* PI, const float* p) {
    crx_hh<4, 2>(PR, PI, p + 16 * SST);   // crx<8,4>
    crx_hh<2, 1>(PR, PI, p + 18 * SST);   // crx<4,2>
    crx_t1<1>   (PR, PI, p + 20 * SST);   // crx<2,1>
    crx_c1<4>   (PR, PI, p + 22 * SST);   // crx<1,8>
    crx_c1<1>   (PR, PI, p + 24 * SST);   // crx<1,2>
    crx_hh<1, 2>(PR, PI, p + 26 * SST);   // crx<2,4>
    crx_hh<2, 4>(PR, PI, p + 28 * SST);   // crx<4,8>
    crx_t1<4>   (PR, PI, p + 30 * SST);   // crx<8,1>
}
__device__ __forceinline__ void layer_packed(ull* PR, ull* PI, const float* p) {
    layer_u(PR, PI, p);
    layer_crx(PR, PI, p);
}

// Sparse k=1 prologue: state after 4 U gates applied to |0> is a tensor
// product of first columns: f_w(0) = (ar, ai), f_w(1) = (-br, bi).
__device__ __forceinline__ void product_state(ull* PR, ull* PI, const float* p) {
    float f0r[2], f0i[2], f1r[2], f1i[2], f2r[2], f2i[2];
    {
        const float* g = p;
        f0r[0] = g[0]; f0i[0] = g[SST]; f0r[1] = -g[2 * SST]; f0i[1] = g[3 * SST];
        g = p + 4 * SST;
        f1r[0] = g[0]; f1i[0] = g[SST]; f1r[1] = -g[2 * SST]; f1i[1] = g[3 * SST];
        g = p + 8 * SST;
        f2r[0] = g[0]; f2i[0] = g[SST]; f2r[1] = -g[2 * SST]; f2i[1] = g[3 * SST];
    }
    const float* g3 = p + 12 * SST;
    ull F3r = pack2(g3[0], -g3[2 * SST]);
    ull F3i = pack2(g3[SST], g3[3 * SST]);

    float gr[8], gi[8];
#pragma unroll
    for (int b0 = 0; b0 < 2; ++b0)
#pragma unroll
    for (int b1 = 0; b1 < 2; ++b1) {
        float ar01 = f0r[b0] * f1r[b1] - f0i[b0] * f1i[b1];
        float ai01 = f0r[b0] * f1i[b1] + f0i[b0] * f1r[b1];
#pragma unroll
        for (int b2 = 0; b2 < 2; ++b2) {
            int j = b0 * 4 + b1 * 2 + b2;
            gr[j] = ar01 * f2r[b2] - ai01 * f2i[b2];
            gi[j] = ar01 * f2i[b2] + ai01 * f2r[b2];
        }
    }
#pragma unroll
    for (int j = 0; j < 8; ++j) {
        ull grj = bc2(gr[j]), gij = bc2(gi[j]), ngij = bc2(-gi[j]);
        PR[j] = fma2(grj, F3r, mul2(ngij, F3i));
        PI[j] = fma2(grj, F3i, mul2(gij,  F3r));
    }
}

// ---------- scalar versions for the tiny final stage ----------
template <int BIT>
__device__ __forceinline__ void apply_u_sc(float* sr, float* si, U2 u) {
#pragma unroll
    for (int m = 0; m < DIMQ; ++m) if (!(m & BIT)) {
        const int m1 = m | BIT;
        float x0r = sr[m], x0i = si[m], x1r = sr[m1], x1i = si[m1];
        sr[m]  =  u.ar * x0r - u.ai * x0i + u.br * x1r - u.bi * x1i;
        si[m]  =  u.ar * x0i + u.ai * x0r + u.br * x1i + u.bi * x1r;
        sr[m1] = -u.br * x0r - u.bi * x0i + u.ar * x1r + u.ai * x1i;
        si[m1] =  u.bi * x0r - u.br * x0i + u.ar * x1i - u.ai * x1r;
    }
}
template <int CB, int TB>
__device__ __forceinline__ void apply_crx_sc(float* sr, float* si, float h) {
    float s, c;
    __sincosf(h, &s, &c);
#pragma unroll
    for (int m = 0; m < DIMQ; ++m) if ((m & CB) && !(m & TB)) {
        const int m1 = m | TB;
        float a0r = sr[m], a0i = si[m], a1r = sr[m1], a1i = si[m1];
        sr[m]  = c * a0r + s * a1i;
        si[m]  = c * a0i - s * a1r;
        sr[m1] = c * a1r + s * a0i;
        si[m1] = c * a1i - s * a0r;
    }
}
__device__ __forceinline__ void ansatz_layer_sc(float* sr, float* si, const float* hp) {
    apply_u_sc<8>(sr, si, make_u3(hp[0], hp[1], hp[2]));
    apply_u_sc<4>(sr, si, make_u3(hp[3], hp[4], hp[5]));
    apply_u_sc<2>(sr, si, make_u3(hp[6], hp[7], hp[8]));
    apply_u_sc<1>(sr, si, make_u3(hp[9], hp[10], hp[11]));
    apply_crx_sc<8, 4>(sr, si, hp[12]);
    apply_crx_sc<4, 2>(sr, si, hp[13]);
    apply_crx_sc<2, 1>(sr, si, hp[14]);
    apply_crx_sc<1, 8>(sr, si, hp[15]);
    apply_crx_sc<1, 2>(sr, si, hp[16]);
    apply_crx_sc<2, 4>(sr, si, hp[17]);
    apply_crx_sc<4, 8>(sr, si, hp[18]);
    apply_crx_sc<8, 1>(sr, si, hp[19]);
}

__global__ __launch_bounds__(BLK, 3)
void qcore_kernel(const float* __restrict__ tp,    // (B, T, 40)
                  const float* __restrict__ pc,    // (4,)
                  const float* __restrict__ mre,   // (T,)
                  const float* __restrict__ mim,   // (T,)
                  const float* __restrict__ qff,   // (20,)
                  float* __restrict__ out)         // (B, 12)
{
    extern __shared__ float smem[];
    float* coef  = smem;                       // 64*SST
    float* red   = smem + COEF_FLOATS;         // NWARP*32
    float* st_s  = red + NWARP * 32;           // 32
    float* acc_s = st_s + 32;                  // 32

    const int b    = blockIdx.x;
    const int tid  = threadIdx.x;
    const int lane = tid & 31;
    const int wid  = tid >> 5;

    if (tid < 32) {
        float v = (tid == 0) ? 1.0f : 0.0f;
        st_s[tid]  = v;
        acc_s[tid] = pc[0] * v;
    }

    const bool active = (tid < TSTEPS);
    float cr = 0.0f, ci = 0.0f;
    if (active) {
        cr = mre[tid];
        ci = mim[tid];
        float hp[NROTS];
        const float4* p4 = (const float4*)(tp + ((size_t)b * TSTEPS + tid) * NROTS);
#pragma unroll
        for (int i = 0; i < NROTS / 4; ++i) {
            float4 v = p4[i];
            hp[4 * i + 0] = 0.5f * v.x;
            hp[4 * i + 1] = 0.5f * v.y;
            hp[4 * i + 2] = 0.5f * v.z;
            hp[4 * i + 3] = 0.5f * v.w;
        }
        // precompute gate coefficients into smem (i-major, conflict-free)
        float* w = coef + tid;
#pragma unroll
        for (int L = 0; L < 2; ++L) {
            const int base = 20 * L;
            const int cbase = 32 * L;
#pragma unroll
            for (int q = 0; q < 4; ++q) {
                U2 u = make_u3(hp[base + 3 * q], hp[base + 3 * q + 1], hp[base + 3 * q + 2]);
                w[(cbase + 4 * q + 0) * SST] = u.ar;
                w[(cbase + 4 * q + 1) * SST] = u.ai;
                w[(cbase + 4 * q + 2) * SST] = u.br;
                w[(cbase + 4 * q + 3) * SST] = u.bi;
            }
#pragma unroll
            for (int r = 0; r < 8; ++r) {
                float s, c;
                __sincosf(hp[base + 12 + r], &s, &c);
                w[(cbase + 16 + 2 * r + 0) * SST] = c;
                w[(cbase + 16 + 2 * r + 1) * SST] = s;
            }
        }
    }
    __syncthreads();

    const unsigned FULL = 0xffffffffu;
    const float* cp0 = coef + tid;
    const float* cp1 = coef + 32 * SST + tid;

    for (int k = 1; k <= DEG; ++k) {
        ull PR[8], PI[8];
        if (active) {
            if (k == 1) {
                // |0> input: state after the 4 U gates is a tensor product
                product_state(PR, PI, cp0);
            } else {
#pragma unroll
                for (int j = 0; j < 8; ++j) {
                    PR[j] = pack2(st_s[2 * j],      st_s[2 * j + 1]);
                    PI[j] = pack2(st_s[16 + 2 * j], st_s[17 + 2 * j]);
                }
                layer_u(PR, PI, cp0);
            }
            layer_crx(PR, PI, cp0);
            layer_packed(PR, PI, cp1);
            // weight by complex coeff (cr + i ci)
            ull crp = bc2(cr), cip = bc2(ci), ncip = bc2(-ci);
#pragma unroll
            for (int j = 0; j < 8; ++j) {
                ull r0 = PR[j], i0 = PI[j];
                PR[j] = fma2(crp, r0, mul2(ncip, i0));
                PI[j] = fma2(crp, i0, mul2(cip,  r0));
            }
        } else {
#pragma unroll
            for (int j = 0; j < 8; ++j) { PR[j] = 0ull; PI[j] = 0ull; }
        }

        // ---- register-exchange butterfly: lane L ends with component L ----
        ull W[8];
        {
            const bool up = (lane & 16);
#pragma unroll
            for (int j = 0; j < 8; ++j) {
                ull keep = up ? PI[j] : PR[j];
                ull give = up ? PR[j] : PI[j];
                W[j] = add2(keep, __shfl_xor_sync(FULL, give, 16));
            }
        }
        ull X[4];
        {
            const bool up = (lane & 8);
#pragma unroll
            for (int j = 0; j < 4; ++j) {
                ull keep = up ? W[j + 4] : W[j];
                ull give = up ? W[j] : W[j + 4];
                X[j] = add2(keep, __shfl_xor_sync(FULL, give, 8));
            }
        }
        ull Y[2];
        {
            const bool up = (lane & 4);
#pragma unroll
            for (int j = 0; j < 2; ++j) {
                ull keep = up ? X[j + 2] : X[j];
                ull give = up ? X[j] : X[j + 2];
                Y[j] = add2(keep, __shfl_xor_sync(FULL, give, 4));
            }
        }
        ull Z;
        {
            const bool up = (lane & 2);
            ull keep = up ? Y[1] : Y[0];
            ull give = up ? Y[0] : Y[1];
            Z = add2(keep, __shfl_xor_sync(FULL, give, 2));
        }
        float res;
        {
            float zlo, zhi;
            unpack2(Z, zlo, zhi);
            float keep = (lane & 1) ? zhi : zlo;
            float give = (lane & 1) ? zlo : zhi;
            res = keep + __shfl_xor_sync(FULL, give, 1);
        }

        red[wid * 32 + lane] = res;
        __syncthreads();
        if (tid < 32) {
            float s = 0.0f;
#pragma unroll
            for (int w = 0; w < NWARP; ++w) s += red[w * 32 + tid];
            st_s[tid] = s;
            acc_s[tid] += pc[k] * s;
        }
        __syncthreads();
    }

    // ---- final stage: normalize, qff ansatz, expectation values (thread 0) ----
    if (tid == 0) {
        float l1 = fabsf(pc[0]) + fabsf(pc[1]) + fabsf(pc[2]) + fabsf(pc[3]);
        float inv_l1 = 1.0f / l1;
        float ar[DIMQ], ai[DIMQ];
        float ss = 0.0f;
#pragma unroll
        for (int j = 0; j < DIMQ; ++j) {
            ar[j] = acc_s[j] * inv_l1;
            ai[j] = acc_s[16 + j] * inv_l1;
            ss += ar[j] * ar[j] + ai[j] * ai[j];
        }
        float inv_n = 1.0f / (sqrtf(ss) + 1e-9f);
#pragma unroll
        for (int j = 0; j < DIMQ; ++j) { ar[j] *= inv_n; ai[j] *= inv_n; }

        float qh[20];
#pragma unroll
        for (int i = 0; i < 20; ++i) qh[i] = 0.5f * qff[i];
        ansatz_layer_sc(ar, ai, qh);

#pragma unroll
        for (int w = 0; w < 4; ++w) {
            const int bit = 8 >> w;
            float x = 0.0f, y = 0.0f, z = 0.0f;
#pragma unroll
            for (int m = 0; m < DIMQ; ++m) {
                if (!(m & bit)) {
                    const int m1 = m | bit;
                    float zr = ar[m] * ar[m1] + ai[m] * ai[m1];
                    float zi = ar[m] * ai[m1] - ai[m] * ar[m1];
                    x += 2.0f * zr;
                    y += 2.0f * zi;
                    z += ar[m] * ar[m] + ai[m] * ai[m]
                       - ar[m1] * ar[m1] - ai[m1] * ai[m1];
                }
            }
            out[b * 12 + w]     = x;
            out[b * 12 + 4 + w] = y;
            out[b * 12 + 8 + w] = z;
        }
    }
}

extern "C" void kernel_launch(void* const* d_in, const int* in_sizes, int n_in,
                              void* d_out, int out_size) {
    const float* tp  = (const float*)d_in[0];
    const float* pc  = (const float*)d_in[1];
    const float* mre = (const float*)d_in[2];
    const float* mim = (const float*)d_in[3];
    const float* qff = (const float*)d_in[4];
    float* out = (float*)d_out;

    cudaFuncSetAttribute(qcore_kernel,
                         cudaFuncAttributeMaxDynamicSharedMemorySize, SMEM_BYTES);

    const int B = in_sizes[0] / (TSTEPS * NROTS);
    qcore_kernel<<<B, BLK, SMEM_BYTES>>>(tp, pc, mre, mim, qff, out);
}